// round 17
// baseline (speedup 1.0000x reference)
#include <cuda_runtime.h>
#include <cuda_fp16.h>

#define NN 50000
#define NE 800000
#define FIN 16
#define FE 8
#define HD 8
#define NG 512

// Scratch (allocation-free: __device__ globals).
// g_Yh:  per-node factor table fp16 [n][o][a]: row = 128B = 1 line; lane r's
//        uint4 at n*128+r*16 covers o=r fully (in-lane dot).
// g_eah: edge_attr as fp16 (8 halves = 16B per edge), written by edge layer 0
//        as a side product (it already packs ea to half2 for its own dot).
// g_base: per-node base term base[n][o], fp32.
// g_agg:  scatter accumulators fp32, [layer][n*8+o].
__device__ __half2 g_Yh[NN * 32];
__device__ uint4   g_eah[NE];
__device__ float   g_base[NN * HD];
__device__ float   g_agg[2][NN * HD];

// Layer-1 per-node precompute, thread per (n,o). Zeroes agg[0], seeds out.
__global__ void k_node1(const float* __restrict__ x, const float* __restrict__ We1,
                        const float* __restrict__ be1, const float* __restrict__ root1,
                        const float* __restrict__ b1, const float* __restrict__ blast,
                        float* __restrict__ out) {
    __shared__ float sW[FIN * HD * HD];   // [i][o][a]
    __shared__ float sWc[FIN * HD];       // root1 + be1 : [i][o]
    for (int t = threadIdx.x; t < FIN * 64; t += blockDim.x) {
        int i = t >> 6, o = (t >> 3) & 7, a = t & 7;
        sW[t] = We1[a * (FIN * HD) + i * HD + o];
    }
    for (int t = threadIdx.x; t < FIN * HD; t += blockDim.x)
        sWc[t] = root1[t] + be1[t];
    __syncthreads();

    int gid = blockIdx.x * blockDim.x + threadIdx.x;
    if (gid < NG) out[gid] = blast[0];
    if (gid < NN * 2)
        ((float4*)g_agg[0])[gid] = make_float4(0.f, 0.f, 0.f, 0.f);
    int n = gid >> 3, o = gid & 7;
    if (n >= NN) return;

    float xv[FIN];
    const float4* xp = (const float4*)(x + n * FIN);
    #pragma unroll
    for (int q = 0; q < 4; q++) {
        float4 v = xp[q];
        xv[q * 4 + 0] = v.x; xv[q * 4 + 1] = v.y;
        xv[q * 4 + 2] = v.z; xv[q * 4 + 3] = v.w;
    }

    float4 acc0 = make_float4(0.f, 0.f, 0.f, 0.f);   // a = 0..3
    float4 acc1 = make_float4(0.f, 0.f, 0.f, 0.f);   // a = 4..7
    float bacc = __ldg(b1 + o);
    const float4* sW4 = (const float4*)sW;
    #pragma unroll
    for (int i = 0; i < FIN; i++) {
        float xi = xv[i];
        float4 w0 = sW4[(i * HD + o) * 2 + 0];
        float4 w1 = sW4[(i * HD + o) * 2 + 1];
        acc0.x = fmaf(xi, w0.x, acc0.x); acc0.y = fmaf(xi, w0.y, acc0.y);
        acc0.z = fmaf(xi, w0.z, acc0.z); acc0.w = fmaf(xi, w0.w, acc0.w);
        acc1.x = fmaf(xi, w1.x, acc1.x); acc1.y = fmaf(xi, w1.y, acc1.y);
        acc1.z = fmaf(xi, w1.z, acc1.z); acc1.w = fmaf(xi, w1.w, acc1.w);
        bacc = fmaf(xi, sWc[i * HD + o], bacc);
    }

    __half2 hy[4];
    hy[0] = __floats2half2_rn(acc0.x, acc0.y);
    hy[1] = __floats2half2_rn(acc0.z, acc0.w);
    hy[2] = __floats2half2_rn(acc1.x, acc1.y);
    hy[3] = __floats2half2_rn(acc1.z, acc1.w);
    *(uint4*)(g_Yh + n * 32 + o * 4) = *(const uint4*)hy;
    g_base[gid] = bacc;
}

// Edge layer 0: 8 lanes/edge, 4 edges/thread, scalar per-lane REDs.
// launch_bounds(256,6): squeeze regs 44->42 to fit 6 blocks/SM (48 warps,
// 75% theoretical occ) — hiding product warps*MLP up ~20%.
// PDL: ei/ea loads + packing + dst pointer math pre-sync; Y gathers + REDs
// post-sync. Side product: lane r==0 stores packed fp16 ea for layer 1.
__global__ void __launch_bounds__(256, 6)
k_edge0(const int* __restrict__ ei, const float* __restrict__ ea) {
    const int Q = NE / 4;
    int gid = blockIdx.x * blockDim.x + threadIdx.x;
    int r = gid & 7;
    int t = gid >> 3;             // [0, NE/4)
    int e0 = t, e1 = t + Q, e2 = t + 2 * Q, e3 = t + 3 * Q;

    int src0 = __ldg(ei + e0);
    int src1 = __ldg(ei + e1);
    int src2 = __ldg(ei + e2);
    int src3 = __ldg(ei + e3);
    int dst0 = __ldg(ei + NE + e0);
    int dst1 = __ldg(ei + NE + e1);
    int dst2 = __ldg(ei + NE + e2);
    int dst3 = __ldg(ei + NE + e3);
    float4 a00 = __ldg((const float4*)(ea + e0 * FE));
    float4 a01 = __ldg((const float4*)(ea + e0 * FE + 4));
    float4 a10 = __ldg((const float4*)(ea + e1 * FE));
    float4 a11 = __ldg((const float4*)(ea + e1 * FE + 4));
    float4 a20 = __ldg((const float4*)(ea + e2 * FE));
    float4 a21 = __ldg((const float4*)(ea + e2 * FE + 4));
    float4 a30 = __ldg((const float4*)(ea + e3 * FE));
    float4 a31 = __ldg((const float4*)(ea + e3 * FE + 4));

    // pack ea to half2 pre-sync (independent of predecessor output)
    __half2 eh[4][4];
    #define PACK_EA(k, A0, A1)                          \
        eh[k][0] = __floats2half2_rn((A0).x, (A0).y);   \
        eh[k][1] = __floats2half2_rn((A0).z, (A0).w);   \
        eh[k][2] = __floats2half2_rn((A1).x, (A1).y);   \
        eh[k][3] = __floats2half2_rn((A1).z, (A1).w);
    PACK_EA(0, a00, a01) PACK_EA(1, a10, a11)
    PACK_EA(2, a20, a21) PACK_EA(3, a30, a31)
    #undef PACK_EA

    // stash fp16 ea for layer 1 (one lane per edge group; pre-sync)
    if (r == 0) {
        g_eah[e0] = *(const uint4*)eh[0];
        g_eah[e1] = *(const uint4*)eh[1];
        g_eah[e2] = *(const uint4*)eh[2];
        g_eah[e3] = *(const uint4*)eh[3];
    }

    // dst pointers computed pre-sync (frees post-sync issue slots)
    float* p0 = g_agg[0] + dst0 * HD + r;
    float* p1 = g_agg[0] + dst1 * HD + r;
    float* p2 = g_agg[0] + dst2 * HD + r;
    float* p3 = g_agg[0] + dst3 * HD + r;

    cudaGridDependencySynchronize();   // wait for k_node1 (g_Yh, agg[0]=0)

    uint4 yq0 = __ldg((const uint4*)(g_Yh + src0 * 32 + r * 4));
    uint4 yq1 = __ldg((const uint4*)(g_Yh + src1 * 32 + r * 4));
    uint4 yq2 = __ldg((const uint4*)(g_Yh + src2 * 32 + r * 4));
    uint4 yq3 = __ldg((const uint4*)(g_Yh + src3 * 32 + r * 4));

    #define EDGE_EMIT(yq, k, p)                                                 \
    {                                                                           \
        const __half2* yh = (const __half2*)&(yq);                              \
        __half2 hac = __hmul2(eh[k][0], yh[0]);                                 \
        hac = __hfma2(eh[k][1], yh[1], hac);                                    \
        hac = __hfma2(eh[k][2], yh[2], hac);                                    \
        hac = __hfma2(eh[k][3], yh[3], hac);                                    \
        float2 fa = __half22float2(hac);                                        \
        float m = fa.x + fa.y;                                                  \
        asm volatile("red.global.add.f32 [%0], %1;"                             \
                     :: "l"(p), "f"(m) : "memory");                             \
    }

    EDGE_EMIT(yq0, 0, p0)
    EDGE_EMIT(yq1, 1, p1)
    EDGE_EMIT(yq2, 2, p2)
    EDGE_EMIT(yq3, 3, p3)
    #undef EDGE_EMIT
}

// h1 = relu(agg1 + base1); layer-2 per-node precompute (thread per (n,o)).
// PDL: smem weight staging + agg[1] zeroing run pre-sync.
__global__ void k_node2(const float* __restrict__ We2, const float* __restrict__ be2,
                        const float* __restrict__ root2, const float* __restrict__ b2) {
    __shared__ float sW[HD * HD * HD];    // [i][o][a]
    __shared__ float sWc[HD * HD];        // root2 + be2 : [i][o]
    for (int t = threadIdx.x; t < HD * 64; t += blockDim.x) {
        int i = t >> 6, o = (t >> 3) & 7, a = t & 7;
        sW[t] = We2[a * (HD * HD) + i * HD + o];
    }
    for (int t = threadIdx.x; t < HD * HD; t += blockDim.x)
        sWc[t] = root2[t] + be2[t];

    int gid = blockIdx.x * blockDim.x + threadIdx.x;
    if (gid < NN * 2)
        ((float4*)g_agg[1])[gid] = make_float4(0.f, 0.f, 0.f, 0.f);
    __syncthreads();

    cudaGridDependencySynchronize();   // wait for k_edge0 REDs

    int n = gid >> 3, o = gid & 7;
    if (n >= NN) return;

    float h[HD];
    {
        const float4* ap = (const float4*)(g_agg[0] + n * HD);
        const float4* cp = (const float4*)(g_base + n * HD);
        float4 a0 = __ldg(ap), a1 = __ldg(ap + 1);
        float4 c0 = __ldg(cp), c1 = __ldg(cp + 1);
        h[0] = fmaxf(a0.x + c0.x, 0.f); h[1] = fmaxf(a0.y + c0.y, 0.f);
        h[2] = fmaxf(a0.z + c0.z, 0.f); h[3] = fmaxf(a0.w + c0.w, 0.f);
        h[4] = fmaxf(a1.x + c1.x, 0.f); h[5] = fmaxf(a1.y + c1.y, 0.f);
        h[6] = fmaxf(a1.z + c1.z, 0.f); h[7] = fmaxf(a1.w + c1.w, 0.f);
    }
    __syncwarp();   // all reads of g_base[n][*] done before warp-mates overwrite

    float4 acc0 = make_float4(0.f, 0.f, 0.f, 0.f);
    float4 acc1 = make_float4(0.f, 0.f, 0.f, 0.f);
    float bacc = __ldg(b2 + o);
    const float4* sW4 = (const float4*)sW;
    #pragma unroll
    for (int i = 0; i < HD; i++) {
        float hi = h[i];
        float4 w0 = sW4[(i * HD + o) * 2 + 0];
        float4 w1 = sW4[(i * HD + o) * 2 + 1];
        acc0.x = fmaf(hi, w0.x, acc0.x); acc0.y = fmaf(hi, w0.y, acc0.y);
        acc0.z = fmaf(hi, w0.z, acc0.z); acc0.w = fmaf(hi, w0.w, acc0.w);
        acc1.x = fmaf(hi, w1.x, acc1.x); acc1.y = fmaf(hi, w1.y, acc1.y);
        acc1.z = fmaf(hi, w1.z, acc1.z); acc1.w = fmaf(hi, w1.w, acc1.w);
        bacc = fmaf(hi, sWc[i * HD + o], bacc);
    }

    __half2 hy[4];
    hy[0] = __floats2half2_rn(acc0.x, acc0.y);
    hy[1] = __floats2half2_rn(acc0.z, acc0.w);
    hy[2] = __floats2half2_rn(acc1.x, acc1.y);
    hy[3] = __floats2half2_rn(acc1.z, acc1.w);
    *(uint4*)(g_Yh + n * 32 + o * 4) = *(const uint4*)hy;
    g_base[gid] = bacc;
}

// Edge layer 1: lean variant — ea from g_eah as ONE 16B load, scalar REDs,
// no shuffles. launch_bounds(256,6) for 48 resident warps.
// PDL: ei loads + dst pointers pre-sync; eah/Y post-sync.
__global__ void __launch_bounds__(256, 6)
k_edge1(const int* __restrict__ ei) {
    const int Q = NE / 4;
    int gid = blockIdx.x * blockDim.x + threadIdx.x;
    int r = gid & 7;
    int t = gid >> 3;             // [0, NE/4)
    int e0 = t, e1 = t + Q, e2 = t + 2 * Q, e3 = t + 3 * Q;

    int src0 = __ldg(ei + e0);
    int src1 = __ldg(ei + e1);
    int src2 = __ldg(ei + e2);
    int src3 = __ldg(ei + e3);
    int dst0 = __ldg(ei + NE + e0);
    int dst1 = __ldg(ei + NE + e1);
    int dst2 = __ldg(ei + NE + e2);
    int dst3 = __ldg(ei + NE + e3);

    float* p0 = g_agg[1] + dst0 * HD + r;
    float* p1 = g_agg[1] + dst1 * HD + r;
    float* p2 = g_agg[1] + dst2 * HD + r;
    float* p3 = g_agg[1] + dst3 * HD + r;

    cudaGridDependencySynchronize();   // wait for k_node2 (g_Yh, agg[1]=0)

    uint4 eq0 = __ldg(g_eah + e0);
    uint4 eq1 = __ldg(g_eah + e1);
    uint4 eq2 = __ldg(g_eah + e2);
    uint4 eq3 = __ldg(g_eah + e3);
    uint4 yq0 = __ldg((const uint4*)(g_Yh + src0 * 32 + r * 4));
    uint4 yq1 = __ldg((const uint4*)(g_Yh + src1 * 32 + r * 4));
    uint4 yq2 = __ldg((const uint4*)(g_Yh + src2 * 32 + r * 4));
    uint4 yq3 = __ldg((const uint4*)(g_Yh + src3 * 32 + r * 4));

    #define EDGE_EMIT(yq, eq, p)                                                \
    {                                                                           \
        const __half2* yh = (const __half2*)&(yq);                              \
        const __half2* ehp = (const __half2*)&(eq);                             \
        __half2 hac = __hmul2(ehp[0], yh[0]);                                   \
        hac = __hfma2(ehp[1], yh[1], hac);                                      \
        hac = __hfma2(ehp[2], yh[2], hac);                                      \
        hac = __hfma2(ehp[3], yh[3], hac);                                      \
        float2 fa = __half22float2(hac);                                        \
        float m = fa.x + fa.y;                                                  \
        asm volatile("red.global.add.f32 [%0], %1;"                             \
                     :: "l"(p), "f"(m) : "memory");                             \
    }

    EDGE_EMIT(yq0, eq0, p0)
    EDGE_EMIT(yq1, eq1, p1)
    EDGE_EMIT(yq2, eq2, p2)
    EDGE_EMIT(yq3, eq3, p3)
    #undef EDGE_EMIT
}

// h2 = relu(agg2 + base2); out[batch[n]] += sum_o h2[o]*Wlast[o].
// batch SORTED -> warp-segmented reduction; batch/Wlast loads pre-sync.
__global__ void k_pool(const int* __restrict__ batch, const float* __restrict__ Wlast,
                       float* __restrict__ out) {
    int n = blockIdx.x * blockDim.x + threadIdx.x;
    int lane = threadIdx.x & 31;
    int bid = -1;
    if (n < NN) bid = __ldg(batch + n);
    float w0 = __ldg(Wlast + 0), w1 = __ldg(Wlast + 1);
    float w2 = __ldg(Wlast + 2), w3 = __ldg(Wlast + 3);
    float w4 = __ldg(Wlast + 4), w5 = __ldg(Wlast + 5);
    float w6 = __ldg(Wlast + 6), w7 = __ldg(Wlast + 7);

    cudaGridDependencySynchronize();   // wait for k_edge1 REDs

    float s = 0.f;
    if (n < NN) {
        const float4* ap = (const float4*)(g_agg[1] + n * HD);
        const float4* cp = (const float4*)(g_base + n * HD);
        float4 a0 = __ldg(ap), a1 = __ldg(ap + 1);
        float4 c0 = __ldg(cp), c1 = __ldg(cp + 1);
        s = fmaxf(a0.x + c0.x, 0.f) * w0 + fmaxf(a0.y + c0.y, 0.f) * w1
          + fmaxf(a0.z + c0.z, 0.f) * w2 + fmaxf(a0.w + c0.w, 0.f) * w3
          + fmaxf(a1.x + c1.x, 0.f) * w4 + fmaxf(a1.y + c1.y, 0.f) * w5
          + fmaxf(a1.z + c1.z, 0.f) * w6 + fmaxf(a1.w + c1.w, 0.f) * w7;
    }
    const unsigned FULL = 0xffffffffu;
    int bprev = __shfl_up_sync(FULL, bid, 1);
    #pragma unroll
    for (int d = 1; d < 32; d <<= 1) {
        float tv = __shfl_down_sync(FULL, s, d);
        int  tb = __shfl_down_sync(FULL, bid, d);
        if (lane + d < 32 && tb == bid) s += tv;
    }
    bool leader = (n < NN) && (lane == 0 || bprev != bid);
    if (leader) atomicAdd(out + bid, s);
}

template <typename F, typename... Args>
static void launch_pdl(F f, int grid, int block, Args... args) {
    cudaLaunchConfig_t cfg = {};
    cfg.gridDim = dim3(grid, 1, 1);
    cfg.blockDim = dim3(block, 1, 1);
    cfg.dynamicSmemBytes = 0;
    cfg.stream = 0;
    cudaLaunchAttribute at[1];
    at[0].id = cudaLaunchAttributeProgrammaticStreamSerialization;
    at[0].val.programmaticStreamSerializationAllowed = 1;
    cfg.attrs = at;
    cfg.numAttrs = 1;
    cudaLaunchKernelEx(&cfg, f, args...);
}

extern "C" void kernel_launch(void* const* d_in, const int* in_sizes, int n_in,
                              void* d_out, int out_size) {
    const float* x     = (const float*)d_in[0];
    const int*   ei    = (const int*)  d_in[1];
    const float* ea    = (const float*)d_in[2];
    const int*   batch = (const int*)  d_in[3];
    const float* We1   = (const float*)d_in[4];
    const float* be1   = (const float*)d_in[5];
    const float* root1 = (const float*)d_in[6];
    const float* b1    = (const float*)d_in[7];
    const float* We2   = (const float*)d_in[8];
    const float* be2   = (const float*)d_in[9];
    const float* root2 = (const float*)d_in[10];
    const float* b2    = (const float*)d_in[11];
    const float* Wlast = (const float*)d_in[12];
    const float* blast = (const float*)d_in[13];
    float* out = (float*)d_out;

    k_node1<<<(NN * HD + 255) / 256, 256>>>(x, We1, be1, root1, b1, blast, out);
    launch_pdl(k_edge0, (NE / 4) * 8 / 256, 256, ei, ea);
    launch_pdl(k_node2, (NN * HD + 255) / 256, 256, We2, be2, root2, b2);
    launch_pdl(k_edge1, (NE / 4) * 8 / 256, 256, ei);
    launch_pdl(k_pool,  (NN + 255) / 256, 256, batch, Wlast, out);
}